// round 5
// baseline (speedup 1.0000x reference)
#include <cuda_runtime.h>
#include <cstdint>
#include <cstddef>

// ===== problem constants (B=2,S=1024,H=2048,Fb=8192,E=8,Fe=1024,top_k=2) =====
#define T_TOK 2048
#define HDIM  2048
#define FB    8192
#define NEXP  8
#define FE    1024
#define HCAT  16384          // FB + E*FE

#define BM 128               // token tile
#define BN 64                // feature tile (x2 for gate+up)
#define BK 32                // K per stage
#define NSTG 3
#define ROWB 144             // 32 floats + 4 pad = 36 floats = 144 B (16B-aligned, conflict-free)
#define STG  (256*ROWB)      // 128 A rows + 128 B rows = 36864 B
#define SMEM_DYN (NSTG*STG)  // 110592 B

// ===== device scratch (static; cudaMalloc forbidden) =====
__device__ float g_h [(size_t)T_TOK*HCAT];   // [hb*coef0 | he*w'] hidden (tf32-rounded)
__device__ float g_w8[T_TOK*NEXP];
__device__ float g_c0[T_TOK];

// ===== helpers =====
#define DEVFN __device__ __forceinline__
DEVFN uint32_t s2u(const void* p){ uint32_t a;
    asm("{ .reg .u64 t; cvta.to.shared.u64 t, %1; cvt.u32.u64 %0, t; }":"=r"(a):"l"(p)); return a; }
DEVFN void cpasync16(uint32_t dst, const void* src){
    asm volatile("cp.async.cg.shared.global [%0], [%1], 16;"::"r"(dst),"l"(src):"memory"); }
DEVFN void cp_commit(){ asm volatile("cp.async.commit_group;":::"memory"); }
DEVFN void cp_wait1(){ asm volatile("cp.async.wait_group 1;":::"memory"); }
DEVFN uint32_t tf32u(float f){ uint32_t u;
    asm("cvt.rna.tf32.f32 %0, %1;":"=r"(u):"f"(f)); return u; }
DEVFN float tf32r(float f){ return __uint_as_float(tf32u(f)); }
DEVFN void mma8(float* d, const uint32_t* a, const uint32_t* b){
    asm volatile("mma.sync.aligned.m16n8k8.row.col.f32.tf32.tf32.f32 "
        "{%0,%1,%2,%3},{%4,%5,%6,%7},{%8,%9},{%0,%1,%2,%3};"
        : "+f"(d[0]),"+f"(d[1]),"+f"(d[2]),"+f"(d[3])
        : "r"(a[0]),"r"(a[1]),"r"(a[2]),"r"(a[3]),"r"(b[0]),"r"(b[1]));
}

// ===== router: logits -> top2 -> softmax -> w'[T,8], coef0[T] =====
__global__ __launch_bounds__(128) void router_k(
    const float* __restrict__ x, const float* __restrict__ rw, const float* __restrict__ alpha)
{
    int t = blockIdx.x, tid = threadIdx.x;
    float acc[NEXP];
    #pragma unroll
    for (int e=0;e<NEXP;e++) acc[e]=0.f;
    const float* xr = x + (size_t)t*HDIM;
    for (int h=tid; h<HDIM; h+=128){
        float xv = xr[h];
        #pragma unroll
        for (int e=0;e<NEXP;e++) acc[e] += xv * rw[e*HDIM + h];
    }
    #pragma unroll
    for (int e=0;e<NEXP;e++)
        #pragma unroll
        for (int o=16;o>0;o>>=1) acc[e] += __shfl_xor_sync(0xFFFFFFFFu, acc[e], o);
    __shared__ float part[4][NEXP];
    int warp=tid>>5, lane=tid&31;
    if (lane==0)
        #pragma unroll
        for (int e=0;e<NEXP;e++) part[warp][e]=acc[e];
    __syncthreads();
    if (tid==0){
        float l[NEXP];
        #pragma unroll
        for (int e=0;e<NEXP;e++) l[e]=part[0][e]+part[1][e]+part[2][e]+part[3][e];
        int e1=0; float v1=l[0];
        #pragma unroll
        for (int e=1;e<NEXP;e++) if (l[e]>v1){v1=l[e];e1=e;}
        int e2=-1; float v2=-3.4e38f;
        #pragma unroll
        for (int e=0;e<NEXP;e++) if (e!=e1 && l[e]>v2){v2=l[e];e2=e;}
        float s2=expf(v2-v1), inv=1.f/(1.f+s2);
        float a1=alpha[e1]*inv, a2=alpha[e2]*s2*inv;
        #pragma unroll
        for (int e=0;e<NEXP;e++)
            g_w8[t*NEXP+e] = (e==e1)?a1:((e==e2)?a2:0.f);
        g_c0[t]=1.f-a1-a2;
    }
}

// ===== tf32 mma.sync GEMM, C[t, f] = Act[t,:] . W[f,:] =====
// mode 0: dual gate/up (W0=base_gate, W1=base_up), SwiGLU*coef0 -> g_h[:, f]
// mode 1: dual gate/up (expert gate/up flat),      SwiGLU*w8   -> g_h[:, FB+f]
// mode 2: single (W0=bdw k<8192, W1=edw k>=8192), Act=g_h      -> d_out
__global__ __launch_bounds__(256, 1) void gemm_k(
    int mode, const float* __restrict__ W0, const float* __restrict__ W1,
    const float* __restrict__ Act, float* __restrict__ Out, int KA, int nk)
{
    extern __shared__ char smem[];
    uint32_t sb = s2u(smem);
    int tid = threadIdx.x;
    int fb0 = blockIdx.x * BN;   // feature block
    int t0  = blockIdx.y * BM;   // token block

    auto load_stage = [&](int j){
        int s = j % NSTG;
        uint32_t base = sb + s*STG;
        int k0 = j*BK;
        #pragma unroll
        for (int c = tid; c < 2048; c += 256){
            int row = (c>>3)&127, ch = c&7;
            uint32_t dst;
            const float* src;
            if (c < 1024){                        // A: 128 token rows
                src = Act + (size_t)(t0+row)*KA + k0 + ch*4;
                dst = base + row*ROWB + ch*16;
            } else {                              // B: 64 gate + 64 up rows
                dst = base + (128+row)*ROWB + ch*16;
                if (mode < 2){
                    src = (row < 64 ? W0 + (size_t)(fb0+row)*HDIM
                                    : W1 + (size_t)(fb0+row-64)*HDIM) + k0 + ch*4;
                } else {
                    if (row >= 64) continue;
                    if (k0 < FB)
                        src = W0 + (size_t)(fb0+row)*FB + k0 + ch*4;
                    else {
                        int kk = k0 - FB, e = kk>>10, f = kk&1023;
                        src = W1 + (size_t)e*((size_t)HDIM*FE) + (size_t)(fb0+row)*FE + f + ch*4;
                    }
                }
            }
            cpasync16(dst, src);
        }
    };

    load_stage(0); cp_commit();
    load_stage(1); cp_commit();

    int lane = tid&31, wid = tid>>5;
    int wm = wid>>1, wn = wid&1;          // 4x2 warp grid: warp tile 32x32
    float acc0[2][4][4] = {};             // gate (or mode2 single)
    float acc1[2][4][4] = {};             // up

    int ra = wm*32 + (lane>>2);
    int ca = lane&3;
    int nb = wn*32 + (lane>>2);

    for (int kt = 0; kt < nk; kt++){
        cp_wait1();
        __syncthreads();
        int jn = kt + 2;
        if (jn < nk) load_stage(jn);
        cp_commit();                      // exactly one commit per iter (in-order retire)

        const float* sA = (const float*)(smem + (kt%NSTG)*STG);
        const float* sB = sA + 128*36;

        #pragma unroll
        for (int kk = 0; kk < 4; kk++){
            int c = kk*8 + ca;
            uint32_t a[2][4];
            #pragma unroll
            for (int mt=0; mt<2; mt++){
                int r = ra + mt*16;
                a[mt][0] = tf32u(sA[r*36 + c]);
                a[mt][1] = tf32u(sA[(r+8)*36 + c]);
                a[mt][2] = tf32u(sA[r*36 + c + 4]);
                a[mt][3] = tf32u(sA[(r+8)*36 + c + 4]);
            }
            uint32_t bg[4][2], bu[4][2];
            #pragma unroll
            for (int nt=0; nt<4; nt++){
                int n = nb + nt*8;
                bg[nt][0] = tf32u(sB[n*36 + c]);
                bg[nt][1] = tf32u(sB[n*36 + c + 4]);
                if (mode < 2){
                    bu[nt][0] = tf32u(sB[(64+n)*36 + c]);
                    bu[nt][1] = tf32u(sB[(64+n)*36 + c + 4]);
                }
            }
            #pragma unroll
            for (int mt=0; mt<2; mt++)
                #pragma unroll
                for (int nt=0; nt<4; nt++){
                    mma8(acc0[mt][nt], a[mt], bg[nt]);
                    if (mode < 2) mma8(acc1[mt][nt], a[mt], bu[nt]);
                }
        }
    }

    // ===== epilogue =====
    int r0 = t0 + wm*32 + (lane>>2);
    int cb = fb0 + wn*32 + (lane&3)*2;
    if (mode < 2){
        int off = mode ? FB : 0;
        int ex  = fb0 >> 10;               // expert index (mode 1)
        #pragma unroll
        for (int mt=0; mt<2; mt++){
            int t1 = r0 + mt*16, t2 = t1 + 8;
            float s1 = (mode==0) ? g_c0[t1] : g_w8[t1*NEXP + ex];
            float s2 = (mode==0) ? g_c0[t2] : g_w8[t2*NEXP + ex];
            #pragma unroll
            for (int nt=0; nt<4; nt++){
                int col = off + cb + nt*8;
                float g0 = acc0[mt][nt][0], g1 = acc0[mt][nt][1];
                float g2 = acc0[mt][nt][2], g3 = acc0[mt][nt][3];
                float u0 = acc1[mt][nt][0], u1 = acc1[mt][nt][1];
                float u2 = acc1[mt][nt][2], u3 = acc1[mt][nt][3];
                float2 v1, v2;
                v1.x = tf32r(g0/(1.f+__expf(-g0)) * u0 * s1);
                v1.y = tf32r(g1/(1.f+__expf(-g1)) * u1 * s1);
                v2.x = tf32r(g2/(1.f+__expf(-g2)) * u2 * s2);
                v2.y = tf32r(g3/(1.f+__expf(-g3)) * u3 * s2);
                *(float2*)&g_h[(size_t)t1*HCAT + col] = v1;
                *(float2*)&g_h[(size_t)t2*HCAT + col] = v2;
            }
        }
    } else {
        #pragma unroll
        for (int mt=0; mt<2; mt++){
            int t1 = r0 + mt*16, t2 = t1 + 8;
            #pragma unroll
            for (int nt=0; nt<4; nt++){
                int col = cb + nt*8;
                float2 v1, v2;
                v1.x = acc0[mt][nt][0]; v1.y = acc0[mt][nt][1];
                v2.x = acc0[mt][nt][2]; v2.y = acc0[mt][nt][3];
                *(float2*)&Out[(size_t)t1*HDIM + col] = v1;
                *(float2*)&Out[(size_t)t2*HDIM + col] = v2;
            }
        }
    }
}

// ===== host =====
extern "C" void kernel_launch(void* const* d_in, const int* in_sizes, int n_in,
                              void* d_out, int out_size)
{
    const float* x   = (const float*)d_in[0];
    const float* bgw = (const float*)d_in[1];
    const float* buw = (const float*)d_in[2];
    const float* bdw = (const float*)d_in[3];
    const float* rw  = (const float*)d_in[4];
    const float* egw = (const float*)d_in[5];
    const float* euw = (const float*)d_in[6];
    const float* edw = (const float*)d_in[7];
    const float* alpha = (const float*)d_in[8];
    (void)in_sizes; (void)n_in; (void)out_size;

    float* p_h;
    cudaGetSymbolAddress((void**)&p_h, g_h);

    cudaFuncSetAttribute(gemm_k, cudaFuncAttributeMaxDynamicSharedMemorySize, SMEM_DYN);

    router_k<<<T_TOK, 128>>>(x, rw, alpha);

    // phase 1: base gate/up + SwiGLU -> g_h[:, 0:8192]
    gemm_k<<<dim3(FB/BN, T_TOK/BM), 256, SMEM_DYN>>>(
        0, bgw, buw, x, nullptr, HDIM, HDIM/BK);
    // phase 2: expert gate/up (flat 8192 rows) + SwiGLU -> g_h[:, 8192:16384]
    gemm_k<<<dim3((NEXP*FE)/BN, T_TOK/BM), 256, SMEM_DYN>>>(
        1, egw, euw, x, nullptr, HDIM, HDIM/BK);
    // phase 3: down proj, K = 16384 -> d_out
    gemm_k<<<dim3(HDIM/BN, T_TOK/BM), 256, SMEM_DYN>>>(
        2, bdw, edw, p_h, (float*)d_out, HCAT, HCAT/BK);
}

// round 8
// speedup vs baseline: 1.0219x; 1.0219x over previous
#include <cuda_runtime.h>
#include <cstdint>
#include <cstddef>

// ===== problem constants (B=2,S=1024,H=2048,Fb=8192,E=8,Fe=1024,top_k=2) =====
#define T_TOK 2048
#define HDIM  2048
#define FB    8192
#define NEXP  8
#define FE    1024
#define HCAT  16384          // FB + E*FE

#define BM 128               // token tile
#define BN 32                // feature tile (x2 for gate+up)
#define BK 32                // K per stage
#define NSTG 3
#define ROWB 144             // 32 floats + 4 pad = 36 floats (16B-aligned, conflict-free)
#define STG  (192*ROWB)      // 128 A rows + 64 B rows = 27648 B
#define SMEM_DYN (NSTG*STG)  // 82944 B  (x2 CTAs = 165888 < 227KB/SM)

// ===== device scratch (static; cudaMalloc forbidden) =====
__device__ float g_h [(size_t)T_TOK*HCAT];   // [hb*coef0 | he*w'] hidden (tf32-rounded)
__device__ float g_w8[T_TOK*NEXP];
__device__ float g_c0[T_TOK];

// ===== helpers =====
#define DEVFN __device__ __forceinline__
DEVFN uint32_t s2u(const void* p){ uint32_t a;
    asm("{ .reg .u64 t; cvta.to.shared.u64 t, %1; cvt.u32.u64 %0, t; }":"=r"(a):"l"(p)); return a; }
DEVFN void cpasync16(uint32_t dst, const void* src){
    asm volatile("cp.async.cg.shared.global [%0], [%1], 16;"::"r"(dst),"l"(src):"memory"); }
DEVFN void cp_commit(){ asm volatile("cp.async.commit_group;":::"memory"); }
DEVFN void cp_wait1(){ asm volatile("cp.async.wait_group 1;":::"memory"); }
DEVFN uint32_t tf32u(float f){ uint32_t u;
    asm("cvt.rna.tf32.f32 %0, %1;":"=r"(u):"f"(f)); return u; }
DEVFN float tf32r(float f){ return __uint_as_float(tf32u(f)); }
DEVFN void mma8(float* d, const uint32_t* a, const uint32_t* b){
    asm volatile("mma.sync.aligned.m16n8k8.row.col.f32.tf32.tf32.f32 "
        "{%0,%1,%2,%3},{%4,%5,%6,%7},{%8,%9},{%0,%1,%2,%3};"
        : "+f"(d[0]),"+f"(d[1]),"+f"(d[2]),"+f"(d[3])
        : "r"(a[0]),"r"(a[1]),"r"(a[2]),"r"(a[3]),"r"(b[0]),"r"(b[1]));
}

// ===== router: logits -> top2 -> softmax -> w'[T,8], coef0[T] =====
__global__ __launch_bounds__(128) void router_k(
    const float* __restrict__ x, const float* __restrict__ rw, const float* __restrict__ alpha)
{
    int t = blockIdx.x, tid = threadIdx.x;
    float acc[NEXP];
    #pragma unroll
    for (int e=0;e<NEXP;e++) acc[e]=0.f;
    const float* xr = x + (size_t)t*HDIM;
    for (int h=tid; h<HDIM; h+=128){
        float xv = xr[h];
        #pragma unroll
        for (int e=0;e<NEXP;e++) acc[e] += xv * rw[e*HDIM + h];
    }
    #pragma unroll
    for (int e=0;e<NEXP;e++)
        #pragma unroll
        for (int o=16;o>0;o>>=1) acc[e] += __shfl_xor_sync(0xFFFFFFFFu, acc[e], o);
    __shared__ float part[4][NEXP];
    int warp=tid>>5, lane=tid&31;
    if (lane==0)
        #pragma unroll
        for (int e=0;e<NEXP;e++) part[warp][e]=acc[e];
    __syncthreads();
    if (tid==0){
        float l[NEXP];
        #pragma unroll
        for (int e=0;e<NEXP;e++) l[e]=part[0][e]+part[1][e]+part[2][e]+part[3][e];
        int e1=0; float v1=l[0];
        #pragma unroll
        for (int e=1;e<NEXP;e++) if (l[e]>v1){v1=l[e];e1=e;}
        int e2=-1; float v2=-3.4e38f;
        #pragma unroll
        for (int e=0;e<NEXP;e++) if (e!=e1 && l[e]>v2){v2=l[e];e2=e;}
        float s2=expf(v2-v1), inv=1.f/(1.f+s2);
        float a1=alpha[e1]*inv, a2=alpha[e2]*s2*inv;
        #pragma unroll
        for (int e=0;e<NEXP;e++)
            g_w8[t*NEXP+e] = (e==e1)?a1:((e==e2)?a2:0.f);
        g_c0[t]=1.f-a1-a2;
    }
}

// ===== tf32 mma.sync GEMM, C[t, f] = Act[t,:] . W[f,:] =====
// Warp grid 4(M) x 2(N): warp tile 32(M) x 16(N) per matrix (gate & up).
// mode 0: dual gate/up (W0=base_gate, W1=base_up), SwiGLU*coef0 -> g_h[:, f]
// mode 1: dual gate/up (expert gate/up flat),      SwiGLU*w8   -> g_h[:, FB+f]
// mode 2: single (W0=bdw k<8192, W1=edw k>=8192), Act=g_h      -> d_out
__global__ __launch_bounds__(256) void gemm_k(
    int mode, const float* __restrict__ W0, const float* __restrict__ W1,
    const float* __restrict__ Act, float* __restrict__ Out, int KA, int nk)
{
    extern __shared__ char smem[];
    uint32_t sb = s2u(smem);
    int tid = threadIdx.x;
    int fb0 = blockIdx.x * BN;   // feature block
    int t0  = blockIdx.y * BM;   // token block

    auto load_stage = [&](int j){
        int s = j % NSTG;
        uint32_t base = sb + s*STG;
        int k0 = j*BK;
        #pragma unroll
        for (int c = tid; c < 1536; c += 256){
            uint32_t dst;
            const float* src;
            if (c < 1024){                        // A: 128 token rows
                int row = c>>3, ch = c&7;
                src = Act + (size_t)(t0+row)*KA + k0 + ch*4;
                dst = base + row*ROWB + ch*16;
            } else {                              // B: 32 gate + 32 up rows
                int c2 = c-1024, row = c2>>3, ch = c2&7;
                dst = base + (128+row)*ROWB + ch*16;
                if (mode < 2){
                    src = (row < 32 ? W0 + (size_t)(fb0+row)*HDIM
                                    : W1 + (size_t)(fb0+row-32)*HDIM) + k0 + ch*4;
                } else {
                    if (row >= 32) continue;
                    if (k0 < FB)
                        src = W0 + (size_t)(fb0+row)*FB + k0 + ch*4;
                    else {
                        int kk = k0 - FB, e = kk>>10, f = kk&1023;
                        src = W1 + (size_t)e*((size_t)HDIM*FE) + (size_t)(fb0+row)*FE + f + ch*4;
                    }
                }
            }
            cpasync16(dst, src);
        }
    };

    load_stage(0); cp_commit();
    load_stage(1); cp_commit();

    int lane = tid&31, wid = tid>>5;
    int wm = wid>>1, wn = wid&1;          // 4(M) x 2(N)
    float acc0[2][2][4] = {};             // gate (or mode2 single)
    float acc1[2][2][4] = {};             // up

    int ra = wm*32 + (lane>>2);
    int ca = lane&3;
    int nb = wn*16 + (lane>>2);

    for (int kt = 0; kt < nk; kt++){
        cp_wait1();
        __syncthreads();
        int jn = kt + 2;
        if (jn < nk) load_stage(jn);
        cp_commit();                      // exactly one commit per iter (in-order retire)

        const float* sA = (const float*)(smem + (kt%NSTG)*STG);
        const float* sB = sA + 128*36;

        #pragma unroll
        for (int kk = 0; kk < 4; kk++){
            int c = kk*8 + ca;
            uint32_t a[2][4];
            #pragma unroll
            for (int mt=0; mt<2; mt++){
                int r = ra + mt*16;
                a[mt][0] = tf32u(sA[r*36 + c]);
                a[mt][1] = tf32u(sA[(r+8)*36 + c]);
                a[mt][2] = tf32u(sA[r*36 + c + 4]);
                a[mt][3] = tf32u(sA[(r+8)*36 + c + 4]);
            }
            uint32_t bg[2][2], bu[2][2];
            #pragma unroll
            for (int nt=0; nt<2; nt++){
                int n = nb + nt*8;
                bg[nt][0] = tf32u(sB[n*36 + c]);
                bg[nt][1] = tf32u(sB[n*36 + c + 4]);
                if (mode < 2){
                    bu[nt][0] = tf32u(sB[(32+n)*36 + c]);
                    bu[nt][1] = tf32u(sB[(32+n)*36 + c + 4]);
                }
            }
            #pragma unroll
            for (int mt=0; mt<2; mt++)
                #pragma unroll
                for (int nt=0; nt<2; nt++){
                    mma8(acc0[mt][nt], a[mt], bg[nt]);
                    if (mode < 2) mma8(acc1[mt][nt], a[mt], bu[nt]);
                }
        }
    }

    // ===== epilogue =====
    int r0 = t0 + wm*32 + (lane>>2);
    int cb = fb0 + wn*16 + (lane&3)*2;
    if (mode < 2){
        int off = mode ? FB : 0;
        int ex  = fb0 >> 10;               // expert index (mode 1)
        #pragma unroll
        for (int mt=0; mt<2; mt++){
            int t1 = r0 + mt*16, t2 = t1 + 8;
            float s1 = (mode==0) ? g_c0[t1] : g_w8[t1*NEXP + ex];
            float s2 = (mode==0) ? g_c0[t2] : g_w8[t2*NEXP + ex];
            #pragma unroll
            for (int nt=0; nt<2; nt++){
                int col = off + cb + nt*8;
                float g0 = acc0[mt][nt][0], g1 = acc0[mt][nt][1];
                float g2 = acc0[mt][nt][2], g3 = acc0[mt][nt][3];
                float u0 = acc1[mt][nt][0], u1 = acc1[mt][nt][1];
                float u2 = acc1[mt][nt][2], u3 = acc1[mt][nt][3];
                float2 v1, v2;
                v1.x = tf32r(g0/(1.f+__expf(-g0)) * u0 * s1);
                v1.y = tf32r(g1/(1.f+__expf(-g1)) * u1 * s1);
                v2.x = tf32r(g2/(1.f+__expf(-g2)) * u2 * s2);
                v2.y = tf32r(g3/(1.f+__expf(-g3)) * u3 * s2);
                *(float2*)&g_h[(size_t)t1*HCAT + col] = v1;
                *(float2*)&g_h[(size_t)t2*HCAT + col] = v2;
            }
        }
    } else {
        #pragma unroll
        for (int mt=0; mt<2; mt++){
            int t1 = r0 + mt*16, t2 = t1 + 8;
            #pragma unroll
            for (int nt=0; nt<2; nt++){
                int col = cb + nt*8;
                float2 v1, v2;
                v1.x = acc0[mt][nt][0]; v1.y = acc0[mt][nt][1];
                v2.x = acc0[mt][nt][2]; v2.y = acc0[mt][nt][3];
                *(float2*)&Out[(size_t)t1*HDIM + col] = v1;
                *(float2*)&Out[(size_t)t2*HDIM + col] = v2;
            }
        }
    }
}

// ===== host =====
extern "C" void kernel_launch(void* const* d_in, const int* in_sizes, int n_in,
                              void* d_out, int out_size)
{
    const float* x   = (const float*)d_in[0];
    const float* bgw = (const float*)d_in[1];
    const float* buw = (const float*)d_in[2];
    const float* bdw = (const float*)d_in[3];
    const float* rw  = (const float*)d_in[4];
    const float* egw = (const float*)d_in[5];
    const float* euw = (const float*)d_in[6];
    const float* edw = (const float*)d_in[7];
    const float* alpha = (const float*)d_in[8];
    (void)in_sizes; (void)n_in; (void)out_size;

    float* p_h;
    cudaGetSymbolAddress((void**)&p_h, g_h);

    cudaFuncSetAttribute(gemm_k, cudaFuncAttributeMaxDynamicSharedMemorySize, SMEM_DYN);

    router_k<<<T_TOK, 128>>>(x, rw, alpha);

    // phase 1: base gate/up + SwiGLU -> g_h[:, 0:8192]
    gemm_k<<<dim3(FB/BN, T_TOK/BM), 256, SMEM_DYN>>>(
        0, bgw, buw, x, nullptr, HDIM, HDIM/BK);
    // phase 2: expert gate/up (flat 8192 rows) + SwiGLU -> g_h[:, 8192:16384]
    gemm_k<<<dim3((NEXP*FE)/BN, T_TOK/BM), 256, SMEM_DYN>>>(
        1, egw, euw, x, nullptr, HDIM, HDIM/BK);
    // phase 3: down proj, K = 16384 -> d_out
    gemm_k<<<dim3(HDIM/BN, T_TOK/BM), 256, SMEM_DYN>>>(
        2, bdw, edw, p_h, (float*)d_out, HCAT, HCAT/BK);
}